// round 1
// baseline (speedup 1.0000x reference)
#include <cuda_runtime.h>

// ResidualQuantizer: codes = argmin_k ||r_n - c_k||^2 ; quantized = codebook[codes]
// dist_k = (r2 + c2_k) - 2 * dot(r, c_k)   (replicates reference association order)

#define DIM 64
#define TK 64
#define MAXK 4096

__device__ float g_c2[MAXK];

__global__ void c2_kernel(const float* __restrict__ cb, int K) {
    int k = blockIdx.x * blockDim.x + threadIdx.x;
    if (k >= K) return;
    const float4* row = reinterpret_cast<const float4*>(cb + (size_t)k * DIM);
    float p0 = 0.f, p1 = 0.f, p2 = 0.f, p3 = 0.f;
#pragma unroll
    for (int j = 0; j < 16; j += 4) {
        float4 a = row[j + 0];
        float4 b = row[j + 1];
        float4 c = row[j + 2];
        float4 d = row[j + 3];
        p0 += a.x * a.x + a.y * a.y + a.z * a.z + a.w * a.w;
        p1 += b.x * b.x + b.y * b.y + b.z * b.z + b.w * b.w;
        p2 += c.x * c.x + c.y * c.y + c.z * c.z + c.w * c.w;
        p3 += d.x * d.x + d.y * d.y + d.z * d.z + d.w * d.w;
    }
    g_c2[k] = (p0 + p1) + (p2 + p3);
}

__global__ __launch_bounds__(256, 2)
void vq_argmin_kernel(const float* __restrict__ residual,
                      const float* __restrict__ cb,
                      float* __restrict__ qout,
                      float* __restrict__ codes,
                      int N, int K, int write_q, int write_codes)
{
    __shared__ float4 s_cb[TK * (DIM / 4)];   // 64 rows x 16 float4 = 16 KB
    __shared__ float  s_c2[TK];

    const int n = blockIdx.x * blockDim.x + threadIdx.x;
    const bool active = (n < N);

    // Load this thread's residual row into registers; compute r2 with 4 partials.
    float r[DIM];
    float r2 = 0.f;
    if (active) {
        const float4* rr = reinterpret_cast<const float4*>(residual + (size_t)n * DIM);
#pragma unroll
        for (int j = 0; j < 16; j++) {
            float4 v = rr[j];
            r[4 * j + 0] = v.x; r[4 * j + 1] = v.y;
            r[4 * j + 2] = v.z; r[4 * j + 3] = v.w;
        }
        float p0 = 0.f, p1 = 0.f, p2 = 0.f, p3 = 0.f;
#pragma unroll
        for (int j = 0; j < 16; j++) {
            p0 += r[4 * j + 0] * r[4 * j + 0];
            p1 += r[4 * j + 1] * r[4 * j + 1];
            p2 += r[4 * j + 2] * r[4 * j + 2];
            p3 += r[4 * j + 3] * r[4 * j + 3];
        }
        r2 = (p0 + p1) + (p2 + p3);
    }

    float best = 3.402823466e+38f;
    int bestK = 0;

    for (int k0 = 0; k0 < K; k0 += TK) {
        __syncthreads();
        // Cooperative tile load: TK*DIM floats = 1024 float4, 4 per thread.
        const float4* src = reinterpret_cast<const float4*>(cb + (size_t)k0 * DIM);
#pragma unroll
        for (int i = 0; i < 4; i++) {
            int idx = threadIdx.x + i * 256;
            s_cb[idx] = src[idx];
        }
        if (threadIdx.x < TK) s_c2[threadIdx.x] = g_c2[k0 + threadIdx.x];
        __syncthreads();

        if (active) {
            for (int kk = 0; kk < TK; kk += 4) {
                float a0 = 0.f, a1 = 0.f, a2 = 0.f, a3 = 0.f;
                const float4* c0 = &s_cb[(kk + 0) * 16];
                const float4* c1 = &s_cb[(kk + 1) * 16];
                const float4* c2 = &s_cb[(kk + 2) * 16];
                const float4* c3 = &s_cb[(kk + 3) * 16];
#pragma unroll
                for (int j = 0; j < 16; j++) {
                    float4 v0 = c0[j];
                    float4 v1 = c1[j];
                    float4 v2 = c2[j];
                    float4 v3 = c3[j];
                    float rj0 = r[4 * j + 0], rj1 = r[4 * j + 1];
                    float rj2 = r[4 * j + 2], rj3 = r[4 * j + 3];
                    a0 += rj0 * v0.x; a0 += rj1 * v0.y; a0 += rj2 * v0.z; a0 += rj3 * v0.w;
                    a1 += rj0 * v1.x; a1 += rj1 * v1.y; a1 += rj2 * v1.z; a1 += rj3 * v1.w;
                    a2 += rj0 * v2.x; a2 += rj1 * v2.y; a2 += rj2 * v2.z; a2 += rj3 * v2.w;
                    a3 += rj0 * v3.x; a3 += rj1 * v3.y; a3 += rj2 * v3.z; a3 += rj3 * v3.w;
                }
                // Replicate reference rounding: (r2 + c2_k) - 2*dot_k, all fp32.
                float d0 = (r2 + s_c2[kk + 0]) - 2.0f * a0;
                float d1 = (r2 + s_c2[kk + 1]) - 2.0f * a1;
                float d2 = (r2 + s_c2[kk + 2]) - 2.0f * a2;
                float d3 = (r2 + s_c2[kk + 3]) - 2.0f * a3;
                // Ascending-k strict-< scan => first index wins ties (argmin semantics).
                if (d0 < best) { best = d0; bestK = k0 + kk + 0; }
                if (d1 < best) { best = d1; bestK = k0 + kk + 1; }
                if (d2 < best) { best = d2; bestK = k0 + kk + 2; }
                if (d3 < best) { best = d3; bestK = k0 + kk + 3; }
            }
        }
    }

    if (!active) return;

    if (write_q) {
        const float4* brow = reinterpret_cast<const float4*>(cb + (size_t)bestK * DIM);
        float4* qo = reinterpret_cast<float4*>(qout + (size_t)n * DIM);
#pragma unroll
        for (int j = 0; j < 16; j++) qo[j] = brow[j];
    }
    if (write_codes) {
        codes[n] = (float)bestK;
    }
}

extern "C" void kernel_launch(void* const* d_in, const int* in_sizes, int n_in,
                              void* d_out, int out_size)
{
    const float* residual = (const float*)d_in[0];
    const float* cb       = (const float*)d_in[1];
    const int N = in_sizes[0] / DIM;
    const int K = in_sizes[1] / DIM;

    float* out = (float*)d_out;
    // Output layout assumption: [quantized (N*DIM floats)] [codes (N floats)].
    // Degrade gracefully if out_size only covers one of them.
    int write_q = 0, write_codes = 0;
    float* qout = out;
    float* codes = out;
    if (out_size >= N * DIM + N) {
        write_q = 1; write_codes = 1;
        codes = out + (size_t)N * DIM;
    } else if (out_size >= N * DIM) {
        write_q = 1;                      // quantized only
    } else {
        write_codes = 1;                  // codes only
    }

    c2_kernel<<<(K + 255) / 256, 256>>>(cb, K);

    int blocks = (N + 255) / 256;
    vq_argmin_kernel<<<blocks, 256>>>(residual, cb, qout, codes, N, K, write_q, write_codes);
}

// round 2
// speedup vs baseline: 1.0018x; 1.0018x over previous
#include <cuda_runtime.h>

// ResidualQuantizer: codes = argmin_k ||r_n - c_k||^2 ; quantized = codebook[codes]
// dist_k = (r2 + c2_k) - 2 * dot(r, c_k)   (replicates reference association order)

#define DIM 64
#define TK 64
#define MAXK 4096

__device__ float g_c2[MAXK];

__global__ void c2_kernel(const float* __restrict__ cb, int K) {
    int k = blockIdx.x * blockDim.x + threadIdx.x;
    if (k >= K) return;
    const float4* row = reinterpret_cast<const float4*>(cb + (size_t)k * DIM);
    float p0 = 0.f, p1 = 0.f, p2 = 0.f, p3 = 0.f;
#pragma unroll
    for (int j = 0; j < 16; j += 4) {
        float4 a = row[j + 0];
        float4 b = row[j + 1];
        float4 c = row[j + 2];
        float4 d = row[j + 3];
        p0 += a.x * a.x + a.y * a.y + a.z * a.z + a.w * a.w;
        p1 += b.x * b.x + b.y * b.y + b.z * b.z + b.w * b.w;
        p2 += c.x * c.x + c.y * c.y + c.z * c.z + c.w * c.w;
        p3 += d.x * d.x + d.y * d.y + d.z * d.z + d.w * d.w;
    }
    g_c2[k] = (p0 + p1) + (p2 + p3);
}

__global__ __launch_bounds__(256, 2)
void vq_argmin_kernel(const float* __restrict__ residual,
                      const float* __restrict__ cb,
                      float* __restrict__ qout,
                      float* __restrict__ codes,
                      int N, int K, int write_q, int write_codes)
{
    __shared__ float4 s_cb[TK * (DIM / 4)];   // 64 rows x 16 float4 = 16 KB
    __shared__ float  s_c2[TK];

    const int n = blockIdx.x * blockDim.x + threadIdx.x;
    const bool active = (n < N);

    // Load this thread's residual row into registers; compute r2 with 4 partials.
    float r[DIM];
    float r2 = 0.f;
    if (active) {
        const float4* rr = reinterpret_cast<const float4*>(residual + (size_t)n * DIM);
#pragma unroll
        for (int j = 0; j < 16; j++) {
            float4 v = rr[j];
            r[4 * j + 0] = v.x; r[4 * j + 1] = v.y;
            r[4 * j + 2] = v.z; r[4 * j + 3] = v.w;
        }
        float p0 = 0.f, p1 = 0.f, p2 = 0.f, p3 = 0.f;
#pragma unroll
        for (int j = 0; j < 16; j++) {
            p0 += r[4 * j + 0] * r[4 * j + 0];
            p1 += r[4 * j + 1] * r[4 * j + 1];
            p2 += r[4 * j + 2] * r[4 * j + 2];
            p3 += r[4 * j + 3] * r[4 * j + 3];
        }
        r2 = (p0 + p1) + (p2 + p3);
    }

    float best = 3.402823466e+38f;
    int bestK = 0;

    for (int k0 = 0; k0 < K; k0 += TK) {
        __syncthreads();
        // Cooperative tile load: TK*DIM floats = 1024 float4, 4 per thread.
        const float4* src = reinterpret_cast<const float4*>(cb + (size_t)k0 * DIM);
#pragma unroll
        for (int i = 0; i < 4; i++) {
            int idx = threadIdx.x + i * 256;
            s_cb[idx] = src[idx];
        }
        if (threadIdx.x < TK) s_c2[threadIdx.x] = g_c2[k0 + threadIdx.x];
        __syncthreads();

        if (active) {
            for (int kk = 0; kk < TK; kk += 4) {
                float a0 = 0.f, a1 = 0.f, a2 = 0.f, a3 = 0.f;
                const float4* c0 = &s_cb[(kk + 0) * 16];
                const float4* c1 = &s_cb[(kk + 1) * 16];
                const float4* c2 = &s_cb[(kk + 2) * 16];
                const float4* c3 = &s_cb[(kk + 3) * 16];
#pragma unroll
                for (int j = 0; j < 16; j++) {
                    float4 v0 = c0[j];
                    float4 v1 = c1[j];
                    float4 v2 = c2[j];
                    float4 v3 = c3[j];
                    float rj0 = r[4 * j + 0], rj1 = r[4 * j + 1];
                    float rj2 = r[4 * j + 2], rj3 = r[4 * j + 3];
                    a0 += rj0 * v0.x; a0 += rj1 * v0.y; a0 += rj2 * v0.z; a0 += rj3 * v0.w;
                    a1 += rj0 * v1.x; a1 += rj1 * v1.y; a1 += rj2 * v1.z; a1 += rj3 * v1.w;
                    a2 += rj0 * v2.x; a2 += rj1 * v2.y; a2 += rj2 * v2.z; a2 += rj3 * v2.w;
                    a3 += rj0 * v3.x; a3 += rj1 * v3.y; a3 += rj2 * v3.z; a3 += rj3 * v3.w;
                }
                // Replicate reference rounding: (r2 + c2_k) - 2*dot_k, all fp32.
                float d0 = (r2 + s_c2[kk + 0]) - 2.0f * a0;
                float d1 = (r2 + s_c2[kk + 1]) - 2.0f * a1;
                float d2 = (r2 + s_c2[kk + 2]) - 2.0f * a2;
                float d3 = (r2 + s_c2[kk + 3]) - 2.0f * a3;
                // Ascending-k strict-< scan => first index wins ties (argmin semantics).
                if (d0 < best) { best = d0; bestK = k0 + kk + 0; }
                if (d1 < best) { best = d1; bestK = k0 + kk + 1; }
                if (d2 < best) { best = d2; bestK = k0 + kk + 2; }
                if (d3 < best) { best = d3; bestK = k0 + kk + 3; }
            }
        }
    }

    if (!active) return;

    if (write_q) {
        const float4* brow = reinterpret_cast<const float4*>(cb + (size_t)bestK * DIM);
        float4* qo = reinterpret_cast<float4*>(qout + (size_t)n * DIM);
#pragma unroll
        for (int j = 0; j < 16; j++) qo[j] = brow[j];
    }
    if (write_codes) {
        codes[n] = (float)bestK;
    }
}

extern "C" void kernel_launch(void* const* d_in, const int* in_sizes, int n_in,
                              void* d_out, int out_size)
{
    const float* residual = (const float*)d_in[0];
    const float* cb       = (const float*)d_in[1];
    const int N = in_sizes[0] / DIM;
    const int K = in_sizes[1] / DIM;

    float* out = (float*)d_out;
    // Output layout assumption: [quantized (N*DIM floats)] [codes (N floats)].
    // Degrade gracefully if out_size only covers one of them.
    int write_q = 0, write_codes = 0;
    float* qout = out;
    float* codes = out;
    if (out_size >= N * DIM + N) {
        write_q = 1; write_codes = 1;
        codes = out + (size_t)N * DIM;
    } else if (out_size >= N * DIM) {
        write_q = 1;                      // quantized only
    } else {
        write_codes = 1;                  // codes only
    }

    c2_kernel<<<(K + 255) / 256, 256>>>(cb, K);

    int blocks = (N + 255) / 256;
    vq_argmin_kernel<<<blocks, 256>>>(residual, cb, qout, codes, N, K, write_q, write_codes);
}